// round 6
// baseline (speedup 1.0000x reference)
#include <cuda_runtime.h>
#include <math.h>
#include <float.h>

#define S_LEN 1024
#define D_DIM 64
#define H_NUM 8
#define KG 10
#define NLUT 4096
#define LUT_LO (-0.5f)
#define LUT_SPAN 11.0f
#define BI 64
#define BJ 64
#define KSTR 68    // K tile transposed [d][j], 2-way max conflict on fill
#define QSTR 136   // Q duplicated [d][2i] : (q,q) pairs, 16B-aligned rows
#define VSTR 132   // V duplicated split-halves [j][...], 16B-aligned rows
#define PSTR 68    // P transposed [j][i]

typedef unsigned long long u64;

__device__ float2 g_lut[2][NLUT];

// ---------------------------------------------------------------------------
// f32x2 packed-math helpers (ptxas never emits FFMA2 from C++; PTX only)
// ---------------------------------------------------------------------------
__device__ __forceinline__ u64 pack2(float x, float y) {
    u64 u; asm("mov.b64 %0, {%1,%2};" : "=l"(u) : "f"(x), "f"(y)); return u;
}
__device__ __forceinline__ float2 unpack2(u64 u) {
    float2 f; asm("mov.b64 {%0,%1}, %2;" : "=f"(f.x), "=f"(f.y) : "l"(u)); return f;
}
__device__ __forceinline__ void fma2(u64& d, u64 a, u64 b) {
    asm("fma.rn.f32x2 %0, %1, %2, %0;" : "+l"(d) : "l"(a), "l"(b));
}
__device__ __forceinline__ u64 mul2(u64 a, u64 b) {
    u64 d; asm("mul.rn.f32x2 %0, %1, %2;" : "=l"(d) : "l"(a), "l"(b)); return d;
}

// ---------------------------------------------------------------------------
// Scalar RBF->MLP bias function, exactly matching the reference math (fp32)
// ---------------------------------------------------------------------------
__device__ __forceinline__ float rbf_mlp_scalar(
    float x,
    const float* __restrict__ mu, const float* __restrict__ sg, const float* __restrict__ bb,
    const float* __restrict__ W1, const float* __restrict__ b1,
    const float* __restrict__ W2, const float* __restrict__ b2)
{
    float psi[KG];
#pragma unroll
    for (int k = 0; k < KG; ++k) {
        float z = (x + bb[k] - mu[k]) / sg[k];
        psi[k] = expf(-0.5f * z * z) * (0.3989422804014327f / sg[k]);
    }
    float out = b2[0];
#pragma unroll
    for (int l = 0; l < KG; ++l) {
        float hp = b1[l];
#pragma unroll
        for (int k = 0; k < KG; ++k) hp = fmaf(psi[k], W1[l * KG + k], hp);
        float g = 0.5f * hp * (1.0f + erff(hp * 0.7071067811865476f));
        out = fmaf(g, W2[l], out);
    }
    return out;
}

__global__ void build_lut_kernel(
    const float* muD, const float* sgD, const float* bD,
    const float* muE, const float* sgE, const float* bE,
    const float* W1, const float* b1, const float* W2, const float* b2)
{
    int gid = blockIdx.x * blockDim.x + threadIdx.x;
    if (gid >= 2 * NLUT) return;
    int table = gid >> 12;
    int i = gid & (NLUT - 1);
    const float* mu = table ? muE : muD;
    const float* sg = table ? sgE : sgD;
    const float* bb = table ? bE  : bD;
    const float h = LUT_SPAN / (float)NLUT;
    float x0 = LUT_LO + (float)i * h;
    float2 r;
    r.x = rbf_mlp_scalar(x0,     mu, sg, bb, W1, b1, W2, b2);
    r.y = rbf_mlp_scalar(x0 + h, mu, sg, bb, W1, b1, W2, b2);
    g_lut[table][i] = r;
}

__device__ __forceinline__ float lut_interp(const float2* __restrict__ L, float x)
{
    float t = (x - LUT_LO) * ((float)NLUT / LUT_SPAN);
    int i = __float2int_rd(t);
    i = min(max(i, 0), NLUT - 1);
    float fr = t - (float)i;
    float2 e = L[i];
    return fmaf(fr, e.y - e.x, e.x);
}

// ---------------------------------------------------------------------------
// Fused flash attention, f32x2 packed math.
// One CTA = (head, 64-row i-tile), 256 threads, 4x4 tile per thread.
// tx = tid&15 (j / output-d columns), ty = tid>>4 (i rows).
// ---------------------------------------------------------------------------
__global__ void __launch_bounds__(256, 1)
attn_kernel(const float* __restrict__ Qg, const float* __restrict__ Kg,
            const float* __restrict__ Vg, const float* __restrict__ Dm,
            const float* __restrict__ Em, const int* __restrict__ Mk,
            float* __restrict__ Out)
{
    extern __shared__ float sm[];
    float*  Qd = sm;                              // [64][QSTR]  duplicated pairs
    float*  Kt = sm + 64 * QSTR;                  // [64][KSTR]  transposed
    float*  Vd = sm + 64 * QSTR + 64 * KSTR;      // [64][VSTR]  duplicated split-halves
    float*  Ps = Vd + 64 * VSTR;                  // [64][PSTR]  P transposed
    float2* LD = (float2*)(Ps + 64 * PSTR);
    float2* LE = LD + NLUT;

    const int tid = threadIdx.x;
    const int tx = tid & 15, ty = tid >> 4;
    const int head = blockIdx.y;
    const int i0 = blockIdx.x * BI;
    const int qbase = head * S_LEN * D_DIM;
    const int mb = head * S_LEN * S_LEN;

    // LUTs -> SMEM
    for (int t = tid; t < NLUT; t += 256) { LD[t] = g_lut[0][t]; LE[t] = g_lut[1][t]; }

    // Q fill: duplicated pairs Qd[d][2i] = (q,q).
    // Lanes vary along i -> SMEM dup-stores are conflict-free (Δ = 8B).
    // Gmem reads are strided (16B per row) — Q is tiny, extra traffic negligible.
    {
        int iq = tid & 63;
        int dc = (tid >> 6) * 16;
#pragma unroll
        for (int x = 0; x < 4; ++x) {
            float4 q = *(const float4*)&Qg[qbase + (i0 + iq) * D_DIM + dc + x * 4];
            *(float2*)&Qd[(dc + x * 4 + 0) * QSTR + 2 * iq] = make_float2(q.x, q.x);
            *(float2*)&Qd[(dc + x * 4 + 1) * QSTR + 2 * iq] = make_float2(q.y, q.y);
            *(float2*)&Qd[(dc + x * 4 + 2) * QSTR + 2 * iq] = make_float2(q.z, q.z);
            *(float2*)&Qd[(dc + x * 4 + 3) * QSTR + 2 * iq] = make_float2(q.w, q.w);
        }
    }

    float m[4], l[4];
    u64 O2[2][4];   // O2[iip][c] = (O[ty*4+2iip][c], O[ty*4+2iip+1][c])
#pragma unroll
    for (int ii = 0; ii < 4; ++ii) { m[ii] = -FLT_MAX; l[ii] = 0.f; }
#pragma unroll
    for (int p = 0; p < 2; ++p)
#pragma unroll
        for (int c = 0; c < 4; ++c) O2[p][c] = 0ULL;

    const float SCALE = 0.08838834764831845f;  // 1/sqrt(2*64)

    for (int j0 = 0; j0 < S_LEN; j0 += BJ) {
        __syncthreads();  // (A) previous PV done; safe to overwrite Kt/Vd/Ps

        // K tile transposed + V tile duplicated split-halves
#pragma unroll
        for (int it = 0; it < 4; ++it) {
            int idx = tid + it * 256;
            int r = idx >> 4, c0 = (idx & 15) * 4;
            float4 kk = *(const float4*)&Kg[qbase + (j0 + r) * D_DIM + c0];
            Kt[(c0 + 0) * KSTR + r] = kk.x;
            Kt[(c0 + 1) * KSTR + r] = kk.y;
            Kt[(c0 + 2) * KSTR + r] = kk.z;
            Kt[(c0 + 3) * KSTR + r] = kk.w;
            float4 vv = *(const float4*)&Vg[qbase + (j0 + r) * D_DIM + c0];
            // half 0: pairs for c0,c0+1 ; half 1: pairs for c0+2,c0+3
            *(float4*)&Vd[r * VSTR + c0]      = make_float4(vv.x, vv.x, vv.y, vv.y);
            *(float4*)&Vd[r * VSTR + 64 + c0] = make_float4(vv.z, vv.z, vv.w, vv.w);
        }

        // Prefetch bias inputs (DRAM latency covered by QK loop)
        float4 dd[4], ee[4]; int4 mm[4];
#pragma unroll
        for (int ii = 0; ii < 4; ++ii) {
            int ro = mb + (i0 + ty * 4 + ii) * S_LEN + j0 + tx * 4;
            dd[ii] = *(const float4*)&Dm[ro];
            ee[ii] = *(const float4*)&Em[ro];
            mm[ii] = *(const int4*)&Mk[ro];
        }

        __syncthreads();  // (B) tiles visible

        // ---- QK^T : 8 FFMA2 per k per thread ----
        u64 acc2[4][2];   // acc2[ii][jp] = (s_{j0},s_{j1}) / (s_{j2},s_{j3})
#pragma unroll
        for (int ii = 0; ii < 4; ++ii) { acc2[ii][0] = 0ULL; acc2[ii][1] = 0ULL; }

#pragma unroll 8
        for (int k = 0; k < D_DIM; ++k) {
            ulonglong2 a01 = *(const ulonglong2*)&Qd[k * QSTR + ty * 8];      // (a0,a0),(a1,a1)
            ulonglong2 a23 = *(const ulonglong2*)&Qd[k * QSTR + ty * 8 + 4];  // (a2,a2),(a3,a3)
            ulonglong2 b   = *(const ulonglong2*)&Kt[k * KSTR + tx * 4];      // (b0,b1),(b2,b3)
            fma2(acc2[0][0], a01.x, b.x); fma2(acc2[0][1], a01.x, b.y);
            fma2(acc2[1][0], a01.y, b.x); fma2(acc2[1][1], a01.y, b.y);
            fma2(acc2[2][0], a23.x, b.x); fma2(acc2[2][1], a23.x, b.y);
            fma2(acc2[3][0], a23.y, b.x); fma2(acc2[3][1], a23.y, b.y);
        }

        // ---- scale + LUT bias + mask + online softmax ----
        float alpha[4];
#pragma unroll
        for (int ii = 0; ii < 4; ++ii) {
            float2 s01 = unpack2(acc2[ii][0]);
            float2 s23 = unpack2(acc2[ii][1]);
            float sj[4] = { s01.x, s01.y, s23.x, s23.y };
            float dv[4] = { dd[ii].x, dd[ii].y, dd[ii].z, dd[ii].w };
            float ev[4] = { ee[ii].x, ee[ii].y, ee[ii].z, ee[ii].w };
            int   mv[4] = { mm[ii].x, mm[ii].y, mm[ii].z, mm[ii].w };
#pragma unroll
            for (int jj = 0; jj < 4; ++jj) {
                float bias = lut_interp(LD, dv[jj]) + lut_interp(LE, ev[jj]);
                float s = fmaf(sj[jj], SCALE, bias);
                sj[jj] = (mv[jj] == 0) ? -1e9f : s;
            }
            float rm = fmaxf(fmaxf(sj[0], sj[1]), fmaxf(sj[2], sj[3]));
#pragma unroll
            for (int o = 1; o <= 8; o <<= 1)
                rm = fmaxf(rm, __shfl_xor_sync(0xffffffffu, rm, o));
            float mn = fmaxf(m[ii], rm);
            alpha[ii] = __expf(m[ii] - mn);
            m[ii] = mn;
            float rs = 0.f;
#pragma unroll
            for (int jj = 0; jj < 4; ++jj) {
                float p = __expf(sj[jj] - mn);
                sj[jj] = p;
                rs += p;
            }
#pragma unroll
            for (int o = 1; o <= 8; o <<= 1)
                rs += __shfl_xor_sync(0xffffffffu, rs, o);
            l[ii] = fmaf(l[ii], alpha[ii], rs);
#pragma unroll
            for (int jj = 0; jj < 4; ++jj)
                Ps[(tx * 4 + jj) * PSTR + ty * 4 + ii] = sj[jj];
        }

        // rescale O (packed)
        {
            u64 aa0 = pack2(alpha[0], alpha[1]);
            u64 aa1 = pack2(alpha[2], alpha[3]);
#pragma unroll
            for (int c = 0; c < 4; ++c) {
                O2[0][c] = mul2(O2[0][c], aa0);
                O2[1][c] = mul2(O2[1][c], aa1);
            }
        }

        __syncthreads();  // (C) Ps visible

        // ---- O += P @ V : 8 FFMA2 per k per thread ----
#pragma unroll 8
        for (int k = 0; k < BJ; ++k) {
            ulonglong2 p   = *(const ulonglong2*)&Ps[k * PSTR + ty * 4];       // (p0,p1),(p2,p3)
            ulonglong2 v01 = *(const ulonglong2*)&Vd[k * VSTR + tx * 4];       // (v0,v0),(v1,v1)
            ulonglong2 v23 = *(const ulonglong2*)&Vd[k * VSTR + 64 + tx * 4];  // (v2,v2),(v3,v3)
            fma2(O2[0][0], p.x, v01.x); fma2(O2[0][1], p.x, v01.y);
            fma2(O2[0][2], p.x, v23.x); fma2(O2[0][3], p.x, v23.y);
            fma2(O2[1][0], p.y, v01.x); fma2(O2[1][1], p.y, v01.y);
            fma2(O2[1][2], p.y, v23.x); fma2(O2[1][3], p.y, v23.y);
        }
    }

    // Epilogue: normalize and write out
#pragma unroll
    for (int iip = 0; iip < 2; ++iip) {
        float inv0 = 1.0f / l[2 * iip + 0];
        float inv1 = 1.0f / l[2 * iip + 1];
        float2 o0 = unpack2(O2[iip][0]);
        float2 o1 = unpack2(O2[iip][1]);
        float2 o2 = unpack2(O2[iip][2]);
        float2 o3 = unpack2(O2[iip][3]);
        int r0 = i0 + ty * 4 + 2 * iip;
        *(float4*)&Out[qbase + r0 * D_DIM + tx * 4] =
            make_float4(o0.x * inv0, o1.x * inv0, o2.x * inv0, o3.x * inv0);
        *(float4*)&Out[qbase + (r0 + 1) * D_DIM + tx * 4] =
            make_float4(o0.y * inv1, o1.y * inv1, o2.y * inv1, o3.y * inv1);
    }
}

// SMEM: Qd(64*136) + Kt(64*68) + Vd(64*132) + Ps(64*68) floats + 2 LUTs of 4096 float2
#define SMEM_BYTES ((64 * QSTR + 64 * KSTR + 64 * VSTR + 64 * PSTR) * 4 + 2 * NLUT * 8)

extern "C" void kernel_launch(void* const* d_in, const int* in_sizes, int n_in,
                              void* d_out, int out_size)
{
    const float* Q   = (const float*)d_in[0];
    const float* K   = (const float*)d_in[1];
    const float* V   = (const float*)d_in[2];
    const float* Dm  = (const float*)d_in[3];
    const float* Em  = (const float*)d_in[4];
    const int*   Mk  = (const int*)  d_in[5];
    const float* muD = (const float*)d_in[6];
    const float* sgD = (const float*)d_in[7];
    const float* bD  = (const float*)d_in[8];
    const float* muE = (const float*)d_in[9];
    const float* sgE = (const float*)d_in[10];
    const float* bE  = (const float*)d_in[11];
    const float* W1  = (const float*)d_in[12];
    const float* b1  = (const float*)d_in[13];
    const float* W2  = (const float*)d_in[14];
    const float* b2  = (const float*)d_in[15];
    float* Out = (float*)d_out;

    cudaFuncSetAttribute(attn_kernel, cudaFuncAttributeMaxDynamicSharedMemorySize, SMEM_BYTES);

    build_lut_kernel<<<(2 * NLUT + 255) / 256, 256>>>(muD, sgD, bD, muE, sgE, bE, W1, b1, W2, b2);

    dim3 grid(S_LEN / BI, H_NUM);
    attn_kernel<<<grid, 256, SMEM_BYTES>>>(Q, K, V, Dm, Em, Mk, Out);
}

// round 7
// speedup vs baseline: 1.1622x; 1.1622x over previous
#include <cuda_runtime.h>
#include <math.h>
#include <float.h>

#define S_LEN 1024
#define D_DIM 64
#define H_NUM 8
#define KG 10
#define NLUT 2048
#define LUT_LO (-0.5f)
#define LUT_SPAN 11.0f
#define BI 32
#define BJ 64
#define QSTR 36   // Qt/Ps padded stride (32+4), 16B-aligned rows
#define KSTR 68   // Kt padded stride (64+4), 16B-aligned rows

// LUT storage: [0] = distance table, [1] = energy table. Entry i = {f(x_i), f(x_{i+1})}
__device__ float2 g_lut[2][NLUT];

// ---------------------------------------------------------------------------
// Scalar RBF->MLP bias function, exactly matching the reference math (fp32)
// ---------------------------------------------------------------------------
__device__ __forceinline__ float rbf_mlp_scalar(
    float x,
    const float* __restrict__ mu, const float* __restrict__ sg, const float* __restrict__ bb,
    const float* __restrict__ W1, const float* __restrict__ b1,
    const float* __restrict__ W2, const float* __restrict__ b2)
{
    float psi[KG];
#pragma unroll
    for (int k = 0; k < KG; ++k) {
        float z = (x + bb[k] - mu[k]) / sg[k];
        psi[k] = expf(-0.5f * z * z) * (0.3989422804014327f / sg[k]);
    }
    float out = b2[0];
#pragma unroll
    for (int l = 0; l < KG; ++l) {
        float hp = b1[l];
#pragma unroll
        for (int k = 0; k < KG; ++k) hp = fmaf(psi[k], W1[l * KG + k], hp);
        float g = 0.5f * hp * (1.0f + erff(hp * 0.7071067811865476f));
        out = fmaf(g, W2[l], out);
    }
    return out;
}

__global__ void build_lut_kernel(
    const float* muD, const float* sgD, const float* bD,
    const float* muE, const float* sgE, const float* bE,
    const float* W1, const float* b1, const float* W2, const float* b2)
{
    int gid = blockIdx.x * blockDim.x + threadIdx.x;
    if (gid >= 2 * NLUT) return;
    int table = gid >= NLUT;
    int i = gid & (NLUT - 1);
    const float* mu = table ? muE : muD;
    const float* sg = table ? sgE : sgD;
    const float* bb = table ? bE  : bD;
    const float h = LUT_SPAN / (float)NLUT;
    float x0 = LUT_LO + (float)i * h;
    float2 r;
    r.x = rbf_mlp_scalar(x0,     mu, sg, bb, W1, b1, W2, b2);
    r.y = rbf_mlp_scalar(x0 + h, mu, sg, bb, W1, b1, W2, b2);
    g_lut[table][i] = r;
}

__device__ __forceinline__ float lut_interp(const float2* __restrict__ L, float x)
{
    float t = (x - LUT_LO) * ((float)NLUT / LUT_SPAN);
    int i = __float2int_rd(t);
    i = min(max(i, 0), NLUT - 1);
    float fr = t - (float)i;
    float2 e = L[i];
    return fmaf(fr, e.y - e.x, e.x);
}

// ---------------------------------------------------------------------------
// Fused flash attention: one CTA = (head, 32-row query tile), 128 threads.
// Thread (ty,tx): 4x4 register tile. tx = tid&15 (j/d cols), ty = tid>>4 (i rows, 0..7).
// 2 CTAs resident per SM (grid 256 on 148 SMs) for cross-CTA latency hiding.
// ---------------------------------------------------------------------------
__global__ void __launch_bounds__(128, 2)
attn_kernel(const float* __restrict__ Qg, const float* __restrict__ Kg,
            const float* __restrict__ Vg, const float* __restrict__ Dm,
            const float* __restrict__ Em, const int* __restrict__ Mk,
            float* __restrict__ Out)
{
    extern __shared__ float sm[];
    float*  Qt = sm;                          // [D][BI]  stride QSTR (transposed)
    float*  Kt = sm + 64 * QSTR;              // [D][BJ]  stride KSTR (transposed)
    float*  Vs = Kt + 64 * KSTR;              // [BJ][D]  stride 64
    float*  Ps = Vs + 64 * 64;                // [BJ][BI] stride QSTR (P transposed)
    float2* LD = (float2*)(Ps + 64 * QSTR);
    float2* LE = LD + NLUT;

    const int tid = threadIdx.x;
    const int tx = tid & 15, ty = tid >> 4;   // ty in [0,8)
    const int head = blockIdx.y;
    const int i0 = blockIdx.x * BI;
    const int qbase = head * S_LEN * D_DIM;
    const int mb = head * S_LEN * S_LEN;

    // LUTs -> SMEM
    for (int t = tid; t < NLUT; t += 128) { LD[t] = g_lut[0][t]; LE[t] = g_lut[1][t]; }

    // Load Q tile, transposed [d][i]  (32 rows x 64 cols = 512 float4)
#pragma unroll
    for (int it = 0; it < 4; ++it) {
        int idx = tid + it * 128;
        int r = idx >> 4, c0 = (idx & 15) * 4;
        float4 q = *(const float4*)&Qg[qbase + (i0 + r) * D_DIM + c0];
        Qt[(c0 + 0) * QSTR + r] = q.x;
        Qt[(c0 + 1) * QSTR + r] = q.y;
        Qt[(c0 + 2) * QSTR + r] = q.z;
        Qt[(c0 + 3) * QSTR + r] = q.w;
    }

    float m[4], l[4], O[4][4];
#pragma unroll
    for (int ii = 0; ii < 4; ++ii) {
        m[ii] = -FLT_MAX; l[ii] = 0.f;
#pragma unroll
        for (int c = 0; c < 4; ++c) O[ii][c] = 0.f;
    }

    const float SCALE = 0.08838834764831845f;  // 1/sqrt(2*64)

    for (int j0 = 0; j0 < S_LEN; j0 += BJ) {
        __syncthreads();  // (A) previous PV done; safe to overwrite Kt/Vs/Ps

        // Load K tile (transposed) and V tile: 64x64 = 1024 float4, 8 iters
#pragma unroll
        for (int it = 0; it < 8; ++it) {
            int idx = tid + it * 128;
            int r = idx >> 4, c0 = (idx & 15) * 4;
            float4 kk = *(const float4*)&Kg[qbase + (j0 + r) * D_DIM + c0];
            Kt[(c0 + 0) * KSTR + r] = kk.x;
            Kt[(c0 + 1) * KSTR + r] = kk.y;
            Kt[(c0 + 2) * KSTR + r] = kk.z;
            Kt[(c0 + 3) * KSTR + r] = kk.w;
            *(float4*)&Vs[r * 64 + c0] = *(const float4*)&Vg[qbase + (j0 + r) * D_DIM + c0];
        }

        // Prefetch bias inputs into registers (DRAM latency covered by QK loop)
        float4 dd[4], ee[4]; int4 mm[4];
#pragma unroll
        for (int ii = 0; ii < 4; ++ii) {
            int ro = mb + (i0 + ty * 4 + ii) * S_LEN + j0 + tx * 4;
            dd[ii] = *(const float4*)&Dm[ro];
            ee[ii] = *(const float4*)&Em[ro];
            mm[ii] = *(const int4*)&Mk[ro];
        }

        __syncthreads();  // (B) Kt/Vs (and Qt/LUT on first iter) visible

        // QK^T for the 4x4 tile
        float acc[4][4];
#pragma unroll
        for (int ii = 0; ii < 4; ++ii)
#pragma unroll
            for (int jj = 0; jj < 4; ++jj) acc[ii][jj] = 0.f;

#pragma unroll 16
        for (int k = 0; k < D_DIM; ++k) {
            float4 a = *(const float4*)&Qt[k * QSTR + ty * 4];
            float4 b = *(const float4*)&Kt[k * KSTR + tx * 4];
            float av[4] = {a.x, a.y, a.z, a.w};
            float bv[4] = {b.x, b.y, b.z, b.w};
#pragma unroll
            for (int ii = 0; ii < 4; ++ii)
#pragma unroll
                for (int jj = 0; jj < 4; ++jj)
                    acc[ii][jj] = fmaf(av[ii], bv[jj], acc[ii][jj]);
        }

        // scores = qk*scale + lutD(dist) + lutE(energy); mask==0 -> -1e9
#pragma unroll
        for (int ii = 0; ii < 4; ++ii) {
            float dv[4] = {dd[ii].x, dd[ii].y, dd[ii].z, dd[ii].w};
            float ev[4] = {ee[ii].x, ee[ii].y, ee[ii].z, ee[ii].w};
            int   mv[4] = {mm[ii].x, mm[ii].y, mm[ii].z, mm[ii].w};
#pragma unroll
            for (int jj = 0; jj < 4; ++jj) {
                float bias = lut_interp(LD, dv[jj]) + lut_interp(LE, ev[jj]);
                float s = fmaf(acc[ii][jj], SCALE, bias);
                acc[ii][jj] = (mv[jj] == 0) ? -1e9f : s;
            }
        }

        // Online softmax per row (rows span 16 lanes: tx groups)
#pragma unroll
        for (int ii = 0; ii < 4; ++ii) {
            float rm = fmaxf(fmaxf(acc[ii][0], acc[ii][1]), fmaxf(acc[ii][2], acc[ii][3]));
#pragma unroll
            for (int o = 1; o <= 8; o <<= 1)
                rm = fmaxf(rm, __shfl_xor_sync(0xffffffffu, rm, o));
            float mn = fmaxf(m[ii], rm);
            float alpha = __expf(m[ii] - mn);
            m[ii] = mn;
            float rs = 0.f;
#pragma unroll
            for (int jj = 0; jj < 4; ++jj) {
                float p = __expf(acc[ii][jj] - mn);
                acc[ii][jj] = p;
                rs += p;
            }
#pragma unroll
            for (int o = 1; o <= 8; o <<= 1)
                rs += __shfl_xor_sync(0xffffffffu, rs, o);
            l[ii] = fmaf(l[ii], alpha, rs);
#pragma unroll
            for (int c = 0; c < 4; ++c) O[ii][c] *= alpha;
            // Store P transposed: Ps[j][i]
#pragma unroll
            for (int jj = 0; jj < 4; ++jj)
                Ps[(tx * 4 + jj) * QSTR + ty * 4 + ii] = acc[ii][jj];
        }

        __syncthreads();  // (C) Ps visible

        // O += P @ V
#pragma unroll 16
        for (int k = 0; k < BJ; ++k) {
            float4 a = *(const float4*)&Ps[k * QSTR + ty * 4];
            float4 b = *(const float4*)&Vs[k * 64 + tx * 4];
            float av[4] = {a.x, a.y, a.z, a.w};
            float bv[4] = {b.x, b.y, b.z, b.w};
#pragma unroll
            for (int ii = 0; ii < 4; ++ii)
#pragma unroll
                for (int c = 0; c < 4; ++c)
                    O[ii][c] = fmaf(av[ii], bv[c], O[ii][c]);
        }
    }

    // Epilogue: normalize and write out
#pragma unroll
    for (int ii = 0; ii < 4; ++ii) {
        float inv = 1.0f / l[ii];
        float4 o = make_float4(O[ii][0] * inv, O[ii][1] * inv, O[ii][2] * inv, O[ii][3] * inv);
        *(float4*)&Out[qbase + (i0 + ty * 4 + ii) * D_DIM + tx * 4] = o;
    }
}

// SMEM: Qt(64*36) + Kt(64*68) + Vs(64*64) + Ps(64*36) floats + 2 LUTs of 2048 float2
#define SMEM_BYTES ((64 * QSTR + 64 * KSTR + 64 * 64 + 64 * QSTR) * 4 + 2 * NLUT * 8)

extern "C" void kernel_launch(void* const* d_in, const int* in_sizes, int n_in,
                              void* d_out, int out_size)
{
    const float* Q   = (const float*)d_in[0];
    const float* K   = (const float*)d_in[1];
    const float* V   = (const float*)d_in[2];
    const float* Dm  = (const float*)d_in[3];
    const float* Em  = (const float*)d_in[4];
    const int*   Mk  = (const int*)  d_in[5];
    const float* muD = (const float*)d_in[6];
    const float* sgD = (const float*)d_in[7];
    const float* bD  = (const float*)d_in[8];
    const float* muE = (const float*)d_in[9];
    const float* sgE = (const float*)d_in[10];
    const float* bE  = (const float*)d_in[11];
    const float* W1  = (const float*)d_in[12];
    const float* b1  = (const float*)d_in[13];
    const float* W2  = (const float*)d_in[14];
    const float* b2  = (const float*)d_in[15];
    float* Out = (float*)d_out;

    cudaFuncSetAttribute(attn_kernel, cudaFuncAttributeMaxDynamicSharedMemorySize, SMEM_BYTES);

    build_lut_kernel<<<(2 * NLUT + 255) / 256, 256>>>(muD, sgD, bD, muE, sgE, bE, W1, b1, W2, b2);

    dim3 grid(S_LEN / BI, H_NUM);   // 32 x 8 = 256 CTAs
    attn_kernel<<<grid, 128, SMEM_BYTES>>>(Q, K, V, Dm, Em, Mk, Out);
}

// round 11
// speedup vs baseline: 1.2943x; 1.1136x over previous
#include <cuda_runtime.h>
#include <math.h>
#include <float.h>

#define S_LEN 1024
#define D_DIM 64
#define H_NUM 8
#define KG 10
#define NLUT 2048
#define LUT_LO (-0.5f)
#define LUT_SPAN 11.0f
#define BI 64
#define BJ 64
#define TSTR 68   // padded stride (floats): 2-way max bank conflict, 16B aligned rows
#define SOFTMAX_SHIFT 10.0f   // fixed softmax shift (softmax is shift-invariant)
#define EXP_CLAMP 70.0f       // guarantees no fp32 overflow: 1024*e^70 < FLT_MAX

// LUT storage: [0] = distance table, [1] = energy table. Entry i = {f(x_i), f(x_{i+1})}
__device__ float2 g_lut[2][NLUT];

// ---------------------------------------------------------------------------
// Scalar RBF->MLP bias function, exactly matching the reference math (fp32)
// ---------------------------------------------------------------------------
__device__ __forceinline__ float rbf_mlp_scalar(
    float x,
    const float* __restrict__ mu, const float* __restrict__ sg, const float* __restrict__ bb,
    const float* __restrict__ W1, const float* __restrict__ b1,
    const float* __restrict__ W2, const float* __restrict__ b2)
{
    float psi[KG];
#pragma unroll
    for (int k = 0; k < KG; ++k) {
        float z = (x + bb[k] - mu[k]) / sg[k];
        psi[k] = expf(-0.5f * z * z) * (0.3989422804014327f / sg[k]);
    }
    float out = b2[0];
#pragma unroll
    for (int l = 0; l < KG; ++l) {
        float hp = b1[l];
#pragma unroll
        for (int k = 0; k < KG; ++k) hp = fmaf(psi[k], W1[l * KG + k], hp);
        float g = 0.5f * hp * (1.0f + erff(hp * 0.7071067811865476f));
        out = fmaf(g, W2[l], out);
    }
    return out;
}

__global__ void build_lut_kernel(
    const float* muD, const float* sgD, const float* bD,
    const float* muE, const float* sgE, const float* bE,
    const float* W1, const float* b1, const float* W2, const float* b2)
{
    int gid = blockIdx.x * blockDim.x + threadIdx.x;
    if (gid >= 2 * NLUT) return;
    int table = gid >= NLUT;
    int i = gid & (NLUT - 1);
    const float* mu = table ? muE : muD;
    const float* sg = table ? sgE : sgD;
    const float* bb = table ? bE  : bD;
    const float h = LUT_SPAN / (float)NLUT;
    float x0 = LUT_LO + (float)i * h;
    float2 r;
    r.x = rbf_mlp_scalar(x0,     mu, sg, bb, W1, b1, W2, b2);
    r.y = rbf_mlp_scalar(x0 + h, mu, sg, bb, W1, b1, W2, b2);
    g_lut[table][i] = r;
}

__device__ __forceinline__ float lut_interp(const float2* __restrict__ L, float x)
{
    float t = (x - LUT_LO) * ((float)NLUT / LUT_SPAN);
    int i = __float2int_rd(t);
    i = min(max(i, 0), NLUT - 1);
    float fr = t - (float)i;
    float2 e = L[i];
    return fmaf(fr, e.y - e.x, e.x);
}

// ---------------------------------------------------------------------------
// Fused flash attention, fixed-shift softmax, register-staged K/V pipeline.
// One CTA = (head, 64-row query tile), 256 threads, 4x4 tile per thread.
// tx = tid&15 (j/d cols), ty = tid>>4 (i rows).
// ---------------------------------------------------------------------------
__global__ void __launch_bounds__(256, 1)
attn_kernel(const float* __restrict__ Qg, const float* __restrict__ Kg,
            const float* __restrict__ Vg, const float* __restrict__ Dm,
            const float* __restrict__ Em, const int* __restrict__ Mk,
            float* __restrict__ Out)
{
    extern __shared__ float sm[];
    float*  Qt = sm;                          // [D][BI] stride TSTR (transposed)
    float*  Kt = sm + 64 * TSTR;              // [D][BJ] stride TSTR (transposed)
    float*  Vs = sm + 2 * 64 * TSTR;          // [BJ][D] stride 64
    float*  Ps = sm + 2 * 64 * TSTR + 64 * 64;// [BJ][BI] stride TSTR (P transposed)
    float2* LD = (float2*)(sm + 3 * 64 * TSTR + 64 * 64);
    float2* LE = LD + NLUT;

    const int tid = threadIdx.x;
    const int tx = tid & 15, ty = tid >> 4;
    const int head = blockIdx.y;
    const int i0 = blockIdx.x * BI;
    const int qbase = head * S_LEN * D_DIM;
    const int mb = head * S_LEN * S_LEN;

    // LUTs -> SMEM
    for (int t = tid; t < NLUT; t += 256) { LD[t] = g_lut[0][t]; LE[t] = g_lut[1][t]; }

    // Per-thread tile-fill coordinates (same for every tile)
    const int fr = tid >> 4;            // row 0..15 (+16 per iter)
    const int fc = (tid & 15) * 4;      // col 0..60

    // Load Q tile, transposed [d][i]
#pragma unroll
    for (int it = 0; it < 4; ++it) {
        int r = fr + it * 16;
        float4 q = *(const float4*)&Qg[qbase + (i0 + r) * D_DIM + fc];
        Qt[(fc + 0) * TSTR + r] = q.x;
        Qt[(fc + 1) * TSTR + r] = q.y;
        Qt[(fc + 2) * TSTR + r] = q.z;
        Qt[(fc + 3) * TSTR + r] = q.w;
    }

    float l[4];
    float O[4][4];
#pragma unroll
    for (int ii = 0; ii < 4; ++ii) {
        l[ii] = 0.f;
#pragma unroll
        for (int c = 0; c < 4; ++c) O[ii][c] = 0.f;
    }

    const float SCALE = 0.08838834764831845f;  // 1/sqrt(2*64)

    // Prologue: stage tile 0's K/V in registers
    float4 kreg[4], vreg[4];
#pragma unroll
    for (int it = 0; it < 4; ++it) {
        int r = fr + it * 16;
        kreg[it] = *(const float4*)&Kg[qbase + r * D_DIM + fc];
        vreg[it] = *(const float4*)&Vg[qbase + r * D_DIM + fc];
    }

    for (int j0 = 0; j0 < S_LEN; j0 += BJ) {
        __syncthreads();  // (A) previous PV done; safe to overwrite Kt/Vs/Ps

        // Store staged K (transposed) and V tiles
#pragma unroll
        for (int it = 0; it < 4; ++it) {
            int r = fr + it * 16;
            Kt[(fc + 0) * TSTR + r] = kreg[it].x;
            Kt[(fc + 1) * TSTR + r] = kreg[it].y;
            Kt[(fc + 2) * TSTR + r] = kreg[it].z;
            Kt[(fc + 3) * TSTR + r] = kreg[it].w;
            *(float4*)&Vs[r * 64 + fc] = vreg[it];
        }

        // Bias inputs for this tile (latency covered by QK loop)
        float4 dd[4], ee[4]; int4 mm[4];
#pragma unroll
        for (int ii = 0; ii < 4; ++ii) {
            int ro = mb + (i0 + ty * 4 + ii) * S_LEN + j0 + tx * 4;
            dd[ii] = *(const float4*)&Dm[ro];
            ee[ii] = *(const float4*)&Em[ro];
            mm[ii] = *(const int4*)&Mk[ro];
        }

        __syncthreads();  // (B) Kt/Vs (and Qt/LUT on first iter) visible

        // Issue next tile's K/V loads (latency covered by QK + softmax)
        if (j0 + BJ < S_LEN) {
#pragma unroll
            for (int it = 0; it < 4; ++it) {
                int r = fr + it * 16;
                kreg[it] = *(const float4*)&Kg[qbase + (j0 + BJ + r) * D_DIM + fc];
                vreg[it] = *(const float4*)&Vg[qbase + (j0 + BJ + r) * D_DIM + fc];
            }
        }

        // QK^T for the 4x4 tile
        float acc[4][4];
#pragma unroll
        for (int ii = 0; ii < 4; ++ii)
#pragma unroll
            for (int jj = 0; jj < 4; ++jj) acc[ii][jj] = 0.f;

#pragma unroll 16
        for (int k = 0; k < D_DIM; ++k) {
            float4 a = *(const float4*)&Qt[k * TSTR + ty * 4];
            float4 b = *(const float4*)&Kt[k * TSTR + tx * 4];
            float av[4] = {a.x, a.y, a.z, a.w};
            float bv[4] = {b.x, b.y, b.z, b.w};
#pragma unroll
            for (int ii = 0; ii < 4; ++ii)
#pragma unroll
                for (int jj = 0; jj < 4; ++jj)
                    acc[ii][jj] = fmaf(av[ii], bv[jj], acc[ii][jj]);
        }

        // scores -> exp(min(s - SHIFT, CLAMP)); accumulate per-thread partial l.
        // No cross-lane reduction, no rescale: softmax shift is fixed.
#pragma unroll
        for (int ii = 0; ii < 4; ++ii) {
            float dv[4] = {dd[ii].x, dd[ii].y, dd[ii].z, dd[ii].w};
            float ev[4] = {ee[ii].x, ee[ii].y, ee[ii].z, ee[ii].w};
            int   mv[4] = {mm[ii].x, mm[ii].y, mm[ii].z, mm[ii].w};
#pragma unroll
            for (int jj = 0; jj < 4; ++jj) {
                float bias = lut_interp(LD, dv[jj]) + lut_interp(LE, ev[jj]);
                float s = fmaf(acc[ii][jj], SCALE, bias);
                s = (mv[jj] == 0) ? -1e9f : s;
                float p = __expf(fminf(s - SOFTMAX_SHIFT, EXP_CLAMP));
                l[ii] += p;
                Ps[(tx * 4 + jj) * TSTR + ty * 4 + ii] = p;   // P transposed
            }
        }

        __syncthreads();  // (C) Ps visible

        // O += P @ V
#pragma unroll 16
        for (int k = 0; k < BJ; ++k) {
            float4 a = *(const float4*)&Ps[k * TSTR + ty * 4];
            float4 b = *(const float4*)&Vs[k * 64 + tx * 4];
            float av[4] = {a.x, a.y, a.z, a.w};
            float bv[4] = {b.x, b.y, b.z, b.w};
#pragma unroll
            for (int ii = 0; ii < 4; ++ii)
#pragma unroll
                for (int c = 0; c < 4; ++c)
                    O[ii][c] = fmaf(av[ii], bv[c], O[ii][c]);
        }
    }

    // Epilogue: single cross-lane reduction of l (16-lane tx groups), normalize, write.
#pragma unroll
    for (int ii = 0; ii < 4; ++ii) {
#pragma unroll
        for (int o = 1; o <= 8; o <<= 1)
            l[ii] += __shfl_xor_sync(0xffffffffu, l[ii], o);
    }
#pragma unroll
    for (int ii = 0; ii < 4; ++ii) {
        float inv = 1.0f / l[ii];
        float4 o = make_float4(O[ii][0] * inv, O[ii][1] * inv, O[ii][2] * inv, O[ii][3] * inv);
        *(float4*)&Out[qbase + (i0 + ty * 4 + ii) * D_DIM + tx * 4] = o;
    }
}

// SMEM: Qt(64*68) + Kt(64*68) + Vs(64*64) + Ps(64*68) floats + 2 LUTs of 2048 float2
#define SMEM_BYTES ((3 * 64 * TSTR + 64 * 64) * 4 + 2 * NLUT * 8)

extern "C" void kernel_launch(void* const* d_in, const int* in_sizes, int n_in,
                              void* d_out, int out_size)
{
    const float* Q   = (const float*)d_in[0];
    const float* K   = (const float*)d_in[1];
    const float* V   = (const float*)d_in[2];
    const float* Dm  = (const float*)d_in[3];
    const float* Em  = (const float*)d_in[4];
    const int*   Mk  = (const int*)  d_in[5];
    const float* muD = (const float*)d_in[6];
    const float* sgD = (const float*)d_in[7];
    const float* bD  = (const float*)d_in[8];
    const float* muE = (const float*)d_in[9];
    const float* sgE = (const float*)d_in[10];
    const float* bE  = (const float*)d_in[11];
    const float* W1  = (const float*)d_in[12];
    const float* b1  = (const float*)d_in[13];
    const float* W2  = (const float*)d_in[14];
    const float* b2  = (const float*)d_in[15];
    float* Out = (float*)d_out;

    cudaFuncSetAttribute(attn_kernel, cudaFuncAttributeMaxDynamicSharedMemorySize, SMEM_BYTES);

    build_lut_kernel<<<(2 * NLUT + 255) / 256, 256>>>(muD, sgD, bD, muE, sgE, bE, W1, b1, W2, b2);

    dim3 grid(S_LEN / BI, H_NUM);   // 16 x 8 = 128 CTAs
    attn_kernel<<<grid, 256, SMEM_BYTES>>>(Q, K, V, Dm, Em, Mk, Out);
}

// round 12
// speedup vs baseline: 1.6832x; 1.3005x over previous
#include <cuda_runtime.h>
#include <math.h>
#include <float.h>

#define S_LEN 1024
#define D_DIM 64
#define H_NUM 8
#define KG 10
#define NLUT 2048
#define LUT_LO (-0.5f)
#define LUT_SPAN 11.0f
#define BI 64
#define BJ 64
#define WS 68               // f32 row stride for Qs/Ks/Vs (272B = 4 banks/row-step)
#define SOFTMAX_SHIFT 10.0f
#define EXP_CLAMP 70.0f

__device__ float2 g_lut[2][NLUT];

// ---------------------------------------------------------------------------
// mma / convert helpers
// ---------------------------------------------------------------------------
__device__ __forceinline__ unsigned f2tf32(float x) {
    unsigned u; asm("cvt.rna.tf32.f32 %0, %1;" : "=r"(u) : "f"(x)); return u;
}
// pack two f32 into bf16x2: lo 16 bits = first (lower-k) element
__device__ __forceinline__ unsigned packbf(float lo, float hi) {
    unsigned u; asm("cvt.rn.bf16x2.f32 %0, %1, %2;" : "=r"(u) : "f"(hi), "f"(lo)); return u;
}
__device__ __forceinline__ float lo16f(unsigned u) { return __uint_as_float(u << 16); }
__device__ __forceinline__ float hi16f(unsigned u) { return __uint_as_float(u & 0xffff0000u); }

__device__ __forceinline__ void mma_tf32(float* c, const unsigned* a, unsigned b0, unsigned b1) {
    asm volatile(
        "mma.sync.aligned.m16n8k8.row.col.f32.tf32.tf32.f32 "
        "{%0,%1,%2,%3},{%4,%5,%6,%7},{%8,%9},{%0,%1,%2,%3};"
        : "+f"(c[0]), "+f"(c[1]), "+f"(c[2]), "+f"(c[3])
        : "r"(a[0]), "r"(a[1]), "r"(a[2]), "r"(a[3]), "r"(b0), "r"(b1));
}
__device__ __forceinline__ void mma_bf16(float* c, const unsigned* a, unsigned b0, unsigned b1) {
    asm volatile(
        "mma.sync.aligned.m16n8k16.row.col.f32.bf16.bf16.f32 "
        "{%0,%1,%2,%3},{%4,%5,%6,%7},{%8,%9},{%0,%1,%2,%3};"
        : "+f"(c[0]), "+f"(c[1]), "+f"(c[2]), "+f"(c[3])
        : "r"(a[0]), "r"(a[1]), "r"(a[2]), "r"(a[3]), "r"(b0), "r"(b1));
}

// ---------------------------------------------------------------------------
// RBF->MLP bias (exact reference math), LUT builder, interp
// ---------------------------------------------------------------------------
__device__ __forceinline__ float rbf_mlp_scalar(
    float x,
    const float* __restrict__ mu, const float* __restrict__ sg, const float* __restrict__ bb,
    const float* __restrict__ W1, const float* __restrict__ b1,
    const float* __restrict__ W2, const float* __restrict__ b2)
{
    float psi[KG];
#pragma unroll
    for (int k = 0; k < KG; ++k) {
        float z = (x + bb[k] - mu[k]) / sg[k];
        psi[k] = expf(-0.5f * z * z) * (0.3989422804014327f / sg[k]);
    }
    float out = b2[0];
#pragma unroll
    for (int l = 0; l < KG; ++l) {
        float hp = b1[l];
#pragma unroll
        for (int k = 0; k < KG; ++k) hp = fmaf(psi[k], W1[l * KG + k], hp);
        float g = 0.5f * hp * (1.0f + erff(hp * 0.7071067811865476f));
        out = fmaf(g, W2[l], out);
    }
    return out;
}

__global__ void build_lut_kernel(
    const float* muD, const float* sgD, const float* bD,
    const float* muE, const float* sgE, const float* bE,
    const float* W1, const float* b1, const float* W2, const float* b2)
{
    int gid = blockIdx.x * blockDim.x + threadIdx.x;
    if (gid >= 2 * NLUT) return;
    int table = gid >= NLUT;
    int i = gid & (NLUT - 1);
    const float* mu = table ? muE : muD;
    const float* sg = table ? sgE : sgD;
    const float* bb = table ? bE  : bD;
    const float h = LUT_SPAN / (float)NLUT;
    float x0 = LUT_LO + (float)i * h;
    float2 r;
    r.x = rbf_mlp_scalar(x0,     mu, sg, bb, W1, b1, W2, b2);
    r.y = rbf_mlp_scalar(x0 + h, mu, sg, bb, W1, b1, W2, b2);
    g_lut[table][i] = r;
}

__device__ __forceinline__ float lut_interp(const float2* __restrict__ L, float x)
{
    float t = (x - LUT_LO) * ((float)NLUT / LUT_SPAN);
    int i = __float2int_rd(t);
    i = min(max(i, 0), NLUT - 1);
    float fr = t - (float)i;
    float2 e = L[i];
    return fmaf(fr, e.y - e.x, e.x);
}

// ---------------------------------------------------------------------------
// Tensor-core fused flash attention.
// CTA = (head, 64-row i-tile), 256 threads = 8 warps:
//   warp iblk = wid&3 -> i rows [iblk*16, +16); jhalf = wid>>2 -> j cols [32*jhalf, +32)
// QK: 3xTF32 m16n8k8 (Q/K hi-lo split). PV: 3xBF16 m16n8k16 (P from C-frags free).
// Fixed-shift softmax; per-warp partial O/l; one cross-warp merge at end.
// ---------------------------------------------------------------------------
__global__ void __launch_bounds__(256, 1)
attn_kernel(const float* __restrict__ Qg, const float* __restrict__ Kg,
            const float* __restrict__ Vg, const float* __restrict__ Dm,
            const float* __restrict__ Em, const int* __restrict__ Mk,
            float* __restrict__ Out)
{
    extern __shared__ float sm[];
    float*  Qs = sm;                 // [64][WS] natural row-major f32
    float*  Ks = sm + 64 * WS;       // [64][WS]
    float*  Vs = sm + 2 * 64 * WS;   // [64][WS]
    float2* LD = (float2*)(sm + 3 * 64 * WS);
    float2* LE = LD + NLUT;

    const int tid  = threadIdx.x;
    const int lane = tid & 31;
    const int wid  = tid >> 5;
    const int g    = lane >> 2;      // groupID 0..7
    const int t    = lane & 3;       // threadID-in-group 0..3
    const int iw   = (wid & 3) * 16; // warp i-block
    const int jh   = (wid >> 2) * 32;// warp j-half within tile

    const int head  = blockIdx.y;
    const int i0    = blockIdx.x * BI;
    const int qbase = head * S_LEN * D_DIM;
    const int mb    = head * S_LEN * S_LEN;

    // LUTs -> SMEM
    for (int x = tid; x < NLUT; x += 256) { LD[x] = g_lut[0][x]; LE[x] = g_lut[1][x]; }

    // Fill Q tile (natural layout, coalesced float4 copy)
    const int fr = tid >> 4;            // 0..15
    const int fc = (tid & 15) * 4;      // 0..60
#pragma unroll
    for (int it = 0; it < 4; ++it) {
        int r = fr + it * 16;
        *(float4*)&Qs[r * WS + fc] = *(const float4*)&Qg[qbase + (i0 + r) * D_DIM + fc];
    }

    // Stage tile 0's K/V in registers
    float4 kreg[4], vreg[4];
#pragma unroll
    for (int it = 0; it < 4; ++it) {
        int r = fr + it * 16;
        kreg[it] = *(const float4*)&Kg[qbase + r * D_DIM + fc];
        vreg[it] = *(const float4*)&Vg[qbase + r * D_DIM + fc];
    }

    __syncthreads();   // Qs + LUT visible

    // Resident Q fragments (tf32 hi/lo), 8 k-tiles of 8
    unsigned qh[8][4], ql[8][4];
#pragma unroll
    for (int kt = 0; kt < 8; ++kt) {
        float q0 = Qs[(iw + g)     * WS + kt * 8 + t];
        float q1 = Qs[(iw + g + 8) * WS + kt * 8 + t];
        float q2 = Qs[(iw + g)     * WS + kt * 8 + t + 4];
        float q3 = Qs[(iw + g + 8) * WS + kt * 8 + t + 4];
        qh[kt][0] = f2tf32(q0); ql[kt][0] = f2tf32(q0 - __uint_as_float(qh[kt][0]));
        qh[kt][1] = f2tf32(q1); ql[kt][1] = f2tf32(q1 - __uint_as_float(qh[kt][1]));
        qh[kt][2] = f2tf32(q2); ql[kt][2] = f2tf32(q2 - __uint_as_float(qh[kt][2]));
        qh[kt][3] = f2tf32(q3); ql[kt][3] = f2tf32(q3 - __uint_as_float(qh[kt][3]));
    }

    float O[8][4];     // PV accum: 8 d-tiles x m16n8 C frags
#pragma unroll
    for (int nt = 0; nt < 8; ++nt)
#pragma unroll
        for (int x = 0; x < 4; ++x) O[nt][x] = 0.f;
    float l0 = 0.f, l1 = 0.f;   // partial row sums (rows g, g+8)

    const float SCALE = 0.08838834764831845f;  // 1/sqrt(2*64)

    for (int j0 = 0; j0 < S_LEN; j0 += BJ) {
        __syncthreads();  // (A) previous PV done; safe to overwrite Ks/Vs

        // Store staged K/V (natural layout, coalesced)
#pragma unroll
        for (int it = 0; it < 4; ++it) {
            int r = fr + it * 16;
            *(float4*)&Ks[r * WS + fc] = kreg[it];
            *(float4*)&Vs[r * WS + fc] = vreg[it];
        }

        __syncthreads();  // (B) Ks/Vs visible

        // Prefetch next tile's K/V
        if (j0 + BJ < S_LEN) {
#pragma unroll
            for (int it = 0; it < 4; ++it) {
                int r = fr + it * 16;
                kreg[it] = *(const float4*)&Kg[qbase + (j0 + BJ + r) * D_DIM + fc];
                vreg[it] = *(const float4*)&Vg[qbase + (j0 + BJ + r) * D_DIM + fc];
            }
        }

        // Issue bias loads early (latency hidden by QK mma)
        float2 ddv0[4], ddv1[4], eev0[4], eev1[4];
        int2   mmv0[4], mmv1[4];
        {
            int rb0 = mb + (i0 + iw + g) * S_LEN + j0 + jh;
            int rb1 = rb0 + 8 * S_LEN;
#pragma unroll
            for (int nt = 0; nt < 4; ++nt) {
                int off = nt * 8 + 2 * t;
                ddv0[nt] = *(const float2*)&Dm[rb0 + off];
                ddv1[nt] = *(const float2*)&Dm[rb1 + off];
                eev0[nt] = *(const float2*)&Em[rb0 + off];
                eev1[nt] = *(const float2*)&Em[rb1 + off];
                mmv0[nt] = *(const int2*)&Mk[rb0 + off];
                mmv1[nt] = *(const int2*)&Mk[rb1 + off];
            }
        }

        // ---- QK^T: 3xTF32 ----
        float S[4][4];
#pragma unroll
        for (int nt = 0; nt < 4; ++nt)
#pragma unroll
            for (int x = 0; x < 4; ++x) S[nt][x] = 0.f;

#pragma unroll
        for (int nt = 0; nt < 4; ++nt) {
            const float* Krow = Ks + (jh + nt * 8 + g) * WS;   // B[k][n=g] = K[j=jh+8nt+g][k]
#pragma unroll
            for (int kt = 0; kt < 8; ++kt) {
                float k0 = Krow[kt * 8 + t];
                float k1 = Krow[kt * 8 + t + 4];
                unsigned kh0 = f2tf32(k0), kh1 = f2tf32(k1);
                unsigned kl0 = f2tf32(k0 - __uint_as_float(kh0));
                unsigned kl1 = f2tf32(k1 - __uint_as_float(kh1));
                mma_tf32(S[nt], qh[kt], kh0, kh1);
                mma_tf32(S[nt], ql[kt], kh0, kh1);
                mma_tf32(S[nt], qh[kt], kl0, kl1);
            }
        }

        // ---- bias + mask + fixed-shift softmax (in C-fragment layout) ----
#pragma unroll
        for (int nt = 0; nt < 4; ++nt) {
            float s0 = fmaf(S[nt][0], SCALE, lut_interp(LD, ddv0[nt].x) + lut_interp(LE, eev0[nt].x));
            float s1 = fmaf(S[nt][1], SCALE, lut_interp(LD, ddv0[nt].y) + lut_interp(LE, eev0[nt].y));
            float s2 = fmaf(S[nt][2], SCALE, lut_interp(LD, ddv1[nt].x) + lut_interp(LE, eev1[nt].x));
            float s3 = fmaf(S[nt][3], SCALE, lut_interp(LD, ddv1[nt].y) + lut_interp(LE, eev1[nt].y));
            s0 = (mmv0[nt].x == 0) ? -1e9f : s0;
            s1 = (mmv0[nt].y == 0) ? -1e9f : s1;
            s2 = (mmv1[nt].x == 0) ? -1e9f : s2;
            s3 = (mmv1[nt].y == 0) ? -1e9f : s3;
            float p0 = __expf(fminf(s0 - SOFTMAX_SHIFT, EXP_CLAMP));
            float p1 = __expf(fminf(s1 - SOFTMAX_SHIFT, EXP_CLAMP));
            float p2 = __expf(fminf(s2 - SOFTMAX_SHIFT, EXP_CLAMP));
            float p3 = __expf(fminf(s3 - SOFTMAX_SHIFT, EXP_CLAMP));
            l0 += p0 + p1; l1 += p2 + p3;
            S[nt][0] = p0; S[nt][1] = p1; S[nt][2] = p2; S[nt][3] = p3;
        }

        // ---- PV: 3xBF16, P straight from C frags ----
#pragma unroll
        for (int ktj = 0; ktj < 2; ++ktj) {
            const float* Sa = S[2 * ktj];
            const float* Sb = S[2 * ktj + 1];
            unsigned pah[4], pal[4];
            pah[0] = packbf(Sa[0], Sa[1]); pal[0] = packbf(Sa[0] - lo16f(pah[0]), Sa[1] - hi16f(pah[0]));
            pah[1] = packbf(Sa[2], Sa[3]); pal[1] = packbf(Sa[2] - lo16f(pah[1]), Sa[3] - hi16f(pah[1]));
            pah[2] = packbf(Sb[0], Sb[1]); pal[2] = packbf(Sb[0] - lo16f(pah[2]), Sb[1] - hi16f(pah[2]));
            pah[3] = packbf(Sb[2], Sb[3]); pal[3] = packbf(Sb[2] - lo16f(pah[3]), Sb[3] - hi16f(pah[3]));

            int jr = jh + ktj * 16;
            const float* V0 = Vs + (jr + 2 * t)     * WS + g;   // B rows 2t, 2t+1, 2t+8, 2t+9
            const float* V1 = Vs + (jr + 2 * t + 1) * WS + g;
            const float* V8 = Vs + (jr + 2 * t + 8) * WS + g;
            const float* V9 = Vs + (jr + 2 * t + 9) * WS + g;
#pragma unroll
            for (int nt = 0; nt < 8; ++nt) {
                float v00 = V0[nt * 8], v01 = V1[nt * 8];
                float v10 = V8[nt * 8], v11 = V9[nt * 8];
                unsigned vh0 = packbf(v00, v01);
                unsigned vl0 = packbf(v00 - lo16f(vh0), v01 - hi16f(vh0));
                unsigned vh1 = packbf(v10, v11);
                unsigned vl1 = packbf(v10 - lo16f(vh1), v11 - hi16f(vh1));
                mma_bf16(O[nt], pah, vh0, vh1);
                mma_bf16(O[nt], pal, vh0, vh1);
                mma_bf16(O[nt], pah, vl0, vl1);
            }
        }
    }

    // ---- Epilogue: merge j-halves (warp w <- w+4), reduce l, normalize, write ----
    float* scratch = sm;                 // reuse Qs region: 34 x 128 f32 = 17408B
    int slot = (wid & 3) * 32 + lane;
    if (wid >= 4) {
#pragma unroll
        for (int nt = 0; nt < 8; ++nt)
#pragma unroll
            for (int x = 0; x < 4; ++x)
                scratch[(nt * 4 + x) * 128 + slot] = O[nt][x];
        scratch[32 * 128 + slot] = l0;
        scratch[33 * 128 + slot] = l1;
    }
    __syncthreads();
    if (wid < 4) {
#pragma unroll
        for (int nt = 0; nt < 8; ++nt)
#pragma unroll
            for (int x = 0; x < 4; ++x)
                O[nt][x] += scratch[(nt * 4 + x) * 128 + slot];
        l0 += scratch[32 * 128 + slot];
        l1 += scratch[33 * 128 + slot];
        // reduce over t within each quad (full rows)
        l0 += __shfl_xor_sync(0xffffffffu, l0, 1);
        l0 += __shfl_xor_sync(0xffffffffu, l0, 2);
        l1 += __shfl_xor_sync(0xffffffffu, l1, 1);
        l1 += __shfl_xor_sync(0xffffffffu, l1, 2);
        float inv0 = 1.0f / l0, inv1 = 1.0f / l1;
        int r0 = qbase + (i0 + iw + g) * D_DIM;
        int r1 = qbase + (i0 + iw + g + 8) * D_DIM;
#pragma unroll
        for (int nt = 0; nt < 8; ++nt) {
            int c = nt * 8 + 2 * t;
            *(float2*)&Out[r0 + c] = make_float2(O[nt][0] * inv0, O[nt][1] * inv0);
            *(float2*)&Out[r1 + c] = make_float2(O[nt][2] * inv1, O[nt][3] * inv1);
        }
    }
}

// SMEM: 3 x 64 x 68 f32 + 2 LUTs of 2048 float2 = 52224 + 32768 = 84992 B
#define SMEM_BYTES (3 * 64 * WS * 4 + 2 * NLUT * 8)

extern "C" void kernel_launch(void* const* d_in, const int* in_sizes, int n_in,
                              void* d_out, int out_size)
{
    const float* Q   = (const float*)d_in[0];
    const float* K   = (const float*)d_in[1];
    const float* V   = (const float*)d_in[2];
    const float* Dm  = (const float*)d_in[3];
    const float* Em  = (const float*)d_in[4];
    const int*   Mk  = (const int*)  d_in[5];
    const float* muD = (const float*)d_in[6];
    const float* sgD = (const float*)d_in[7];
    const float* bD  = (const float*)d_in[8];
    const float* muE = (const float*)d_in[9];
    const float* sgE = (const float*)d_in[10];
    const float* bE  = (const float*)d_in[11];
    const float* W1  = (const float*)d_in[12];
    const float* b1  = (const float*)d_in[13];
    const float* W2  = (const float*)d_in[14];
    const float* b2  = (const float*)d_in[15];
    float* Out = (float*)d_out;

    cudaFuncSetAttribute(attn_kernel, cudaFuncAttributeMaxDynamicSharedMemorySize, SMEM_BYTES);

    build_lut_kernel<<<(2 * NLUT + 255) / 256, 256>>>(muD, sgD, bD, muE, sgE, bE, W1, b1, W2, b2);

    dim3 grid(S_LEN / BI, H_NUM);   // 16 x 8 = 128 CTAs
    attn_kernel<<<grid, 256, SMEM_BYTES>>>(Q, K, V, Dm, Em, Mk, Out);
}

// round 16
// speedup vs baseline: 1.8145x; 1.0780x over previous
#include <cuda_runtime.h>
#include <math.h>
#include <float.h>

#define S_LEN 1024
#define D_DIM 64
#define H_NUM 8
#define KG 10
#define NLUT 2048
#define LUT_LO (-0.5f)
#define LUT_SPAN 11.0f
#define BI 64
#define BJ 64
#define WS 68               // u32/f32 row stride for tiles
#define SOFTMAX_SHIFT 10.0f
#define EXP_CLAMP 70.0f

__device__ float2 g_lut[2][NLUT];

// ---------------------------------------------------------------------------
// mma / convert helpers
// ---------------------------------------------------------------------------
__device__ __forceinline__ unsigned f2tf32(float x) {
    unsigned u; asm("cvt.rna.tf32.f32 %0, %1;" : "=r"(u) : "f"(x)); return u;
}
// pack two f32 into bf16x2: lo 16 bits = first (lower-k) element
__device__ __forceinline__ unsigned packbf(float lo, float hi) {
    unsigned u; asm("cvt.rn.bf16x2.f32 %0, %1, %2;" : "=r"(u) : "f"(hi), "f"(lo)); return u;
}
__device__ __forceinline__ float lo16f(unsigned u) { return __uint_as_float(u << 16); }
__device__ __forceinline__ float hi16f(unsigned u) { return __uint_as_float(u & 0xffff0000u); }

__device__ __forceinline__ void mma_tf32(float* c, const unsigned* a, unsigned b0, unsigned b1) {
    asm volatile(
        "mma.sync.aligned.m16n8k8.row.col.f32.tf32.tf32.f32 "
        "{%0,%1,%2,%3},{%4,%5,%6,%7},{%8,%9},{%0,%1,%2,%3};"
        : "+f"(c[0]), "+f"(c[1]), "+f"(c[2]), "+f"(c[3])
        : "r"(a[0]), "r"(a[1]), "r"(a[2]), "r"(a[3]), "r"(b0), "r"(b1));
}
__device__ __forceinline__ void mma_bf16(float* c, const unsigned* a, unsigned b0, unsigned b1) {
    asm volatile(
        "mma.sync.aligned.m16n8k16.row.col.f32.bf16.bf16.f32 "
        "{%0,%1,%2,%3},{%4,%5,%6,%7},{%8,%9},{%0,%1,%2,%3};"
        : "+f"(c[0]), "+f"(c[1]), "+f"(c[2]), "+f"(c[3])
        : "r"(a[0]), "r"(a[1]), "r"(a[2]), "r"(a[3]), "r"(b0), "r"(b1));
}

// ---------------------------------------------------------------------------
// RBF->MLP bias (exact reference math), LUT builder, interp
// ---------------------------------------------------------------------------
__device__ __forceinline__ float rbf_mlp_scalar(
    float x,
    const float* __restrict__ mu, const float* __restrict__ sg, const float* __restrict__ bb,
    const float* __restrict__ W1, const float* __restrict__ b1,
    const float* __restrict__ W2, const float* __restrict__ b2)
{
    float psi[KG];
#pragma unroll
    for (int k = 0; k < KG; ++k) {
        float z = (x + bb[k] - mu[k]) / sg[k];
        psi[k] = expf(-0.5f * z * z) * (0.3989422804014327f / sg[k]);
    }
    float out = b2[0];
#pragma unroll
    for (int l = 0; l < KG; ++l) {
        float hp = b1[l];
#pragma unroll
        for (int k = 0; k < KG; ++k) hp = fmaf(psi[k], W1[l * KG + k], hp);
        float g = 0.5f * hp * (1.0f + erff(hp * 0.7071067811865476f));
        out = fmaf(g, W2[l], out);
    }
    return out;
}

__global__ void build_lut_kernel(
    const float* muD, const float* sgD, const float* bD,
    const float* muE, const float* sgE, const float* bE,
    const float* W1, const float* b1, const float* W2, const float* b2)
{
    int gid = blockIdx.x * blockDim.x + threadIdx.x;
    if (gid >= 2 * NLUT) return;
    int table = gid >= NLUT;
    int i = gid & (NLUT - 1);
    const float* mu = table ? muE : muD;
    const float* sg = table ? sgE : sgD;
    const float* bb = table ? bE  : bD;
    const float h = LUT_SPAN / (float)NLUT;
    float x0 = LUT_LO + (float)i * h;
    float2 r;
    r.x = rbf_mlp_scalar(x0,     mu, sg, bb, W1, b1, W2, b2);
    r.y = rbf_mlp_scalar(x0 + h, mu, sg, bb, W1, b1, W2, b2);
    g_lut[table][i] = r;
}

__device__ __forceinline__ float lut_interp(const float2* __restrict__ L, float x)
{
    float t = (x - LUT_LO) * ((float)NLUT / LUT_SPAN);
    int i = __float2int_rd(t);
    i = min(max(i, 0), NLUT - 1);
    float fr = t - (float)i;
    float2 e = L[i];
    return fmaf(fr, e.y - e.x, e.x);
}

// ---------------------------------------------------------------------------
// Tensor-core fused flash attention, pre-converted SMEM operands.
// CTA = (head, 64-row i-tile), 256 threads = 8 warps:
//   warp iblk = wid&3 -> i rows [iblk*16,+16); jhalf = wid>>2 -> j cols [32*jhalf,+32)
// K kept in SMEM as tf32 hi/lo u32 planes; V as pre-paired bf16x2 hi/lo planes.
// QK: 3xTF32 m16n8k8. PV: 3xBF16 m16n8k16 (P from C frags). Fixed-shift softmax.
// ---------------------------------------------------------------------------
__global__ void __launch_bounds__(256, 1)
attn_kernel(const float* __restrict__ Qg, const float* __restrict__ Kg,
            const float* __restrict__ Vg, const float* __restrict__ Dm,
            const float* __restrict__ Em, const int* __restrict__ Mk,
            float* __restrict__ Out)
{
    extern __shared__ float sm[];
    unsigned* Kh  = (unsigned*)sm;            // [64][WS] tf32 hi
    unsigned* Kl  = Kh + 64 * WS;             // [64][WS] tf32 residual
    unsigned* Vph = Kl + 64 * WS;             // [32][WS] bf16x2 pair hi
    unsigned* Vpl = Vph + 32 * WS;            // [32][WS] bf16x2 pair residual
    float2*   LD  = (float2*)(Vpl + 32 * WS);
    float2*   LE  = LD + NLUT;
    float*    Qs  = sm;                       // aliases Kh/Kl (prologue only)

    const int tid  = threadIdx.x;
    const int lane = tid & 31;
    const int wid  = tid >> 5;
    const int g    = lane >> 2;      // groupID 0..7
    const int t    = lane & 3;       // threadID-in-group 0..3
    const int iw   = (wid & 3) * 16; // warp i-block
    const int jh   = (wid >> 2) * 32;// warp j-half within tile

    const int head  = blockIdx.y;
    const int i0    = blockIdx.x * BI;
    const int qbase = head * S_LEN * D_DIM;
    const int mb    = head * S_LEN * S_LEN;

    // LUTs -> SMEM
    for (int x = tid; x < NLUT; x += 256) { LD[x] = g_lut[0][x]; LE[x] = g_lut[1][x]; }

    // K fill coords: row fr+16it, cols fc..fc+3
    const int fr = tid >> 4;            // 0..15
    const int fc = (tid & 15) * 4;      // 0..60
    // V fill coords: j-pair jp, cols vc..vc+7
    const int jp = tid >> 3;            // 0..31
    const int vc = (tid & 7) * 8;       // 0..56

    // Fill Q tile (natural layout, coalesced)
#pragma unroll
    for (int it = 0; it < 4; ++it) {
        int r = fr + it * 16;
        *(float4*)&Qs[r * WS + fc] = *(const float4*)&Qg[qbase + (i0 + r) * D_DIM + fc];
    }

    // Stage tile 0's K/V in registers
    float4 kreg[4];
#pragma unroll
    for (int it = 0; it < 4; ++it)
        kreg[it] = *(const float4*)&Kg[qbase + (fr + it * 16) * D_DIM + fc];
    float4 vreg[4];   // [0]=row 2jp c vc..vc+3, [1]=row 2jp c+4.., [2]=row 2jp+1 c.., [3]=row 2jp+1 c+4..
    vreg[0] = *(const float4*)&Vg[qbase + (2 * jp)     * D_DIM + vc];
    vreg[1] = *(const float4*)&Vg[qbase + (2 * jp)     * D_DIM + vc + 4];
    vreg[2] = *(const float4*)&Vg[qbase + (2 * jp + 1) * D_DIM + vc];
    vreg[3] = *(const float4*)&Vg[qbase + (2 * jp + 1) * D_DIM + vc + 4];

    __syncthreads();   // Qs + LUT visible

    // Resident Q fragments (tf32 hi/lo), 8 k-tiles of 8
    unsigned qh[8][4], ql[8][4];
#pragma unroll
    for (int kt = 0; kt < 8; ++kt) {
        float q0 = Qs[(iw + g)     * WS + kt * 8 + t];
        float q1 = Qs[(iw + g + 8) * WS + kt * 8 + t];
        float q2 = Qs[(iw + g)     * WS + kt * 8 + t + 4];
        float q3 = Qs[(iw + g + 8) * WS + kt * 8 + t + 4];
        qh[kt][0] = f2tf32(q0); ql[kt][0] = f2tf32(q0 - __uint_as_float(qh[kt][0]));
        qh[kt][1] = f2tf32(q1); ql[kt][1] = f2tf32(q1 - __uint_as_float(qh[kt][1]));
        qh[kt][2] = f2tf32(q2); ql[kt][2] = f2tf32(q2 - __uint_as_float(qh[kt][2]));
        qh[kt][3] = f2tf32(q3); ql[kt][3] = f2tf32(q3 - __uint_as_float(qh[kt][3]));
    }

    float O[8][4];
#pragma unroll
    for (int nt = 0; nt < 8; ++nt)
#pragma unroll
        for (int x = 0; x < 4; ++x) O[nt][x] = 0.f;
    float l0 = 0.f, l1 = 0.f;

    const float SCALE = 0.08838834764831845f;  // 1/sqrt(2*64)

    for (int j0 = 0; j0 < S_LEN; j0 += BJ) {
        __syncthreads();  // (A) previous tile's mma reads done; safe to overwrite

        // Store K as tf32 hi/lo planes
#pragma unroll
        for (int it = 0; it < 4; ++it) {
            int r = fr + it * 16;
            float kv[4] = {kreg[it].x, kreg[it].y, kreg[it].z, kreg[it].w};
            uint4 hh, ll;
            unsigned* hp = (unsigned*)&hh;
            unsigned* lp = (unsigned*)&ll;
#pragma unroll
            for (int e = 0; e < 4; ++e) {
                unsigned h = f2tf32(kv[e]);
                hp[e] = h;
                lp[e] = f2tf32(kv[e] - __uint_as_float(h));
            }
            *(uint4*)&Kh[r * WS + fc] = hh;
            *(uint4*)&Kl[r * WS + fc] = ll;
        }
        // Store V as pre-paired bf16x2 hi/lo planes
        {
            float va[4] = {vreg[0].x, vreg[0].y, vreg[0].z, vreg[0].w};
            float vb[4] = {vreg[1].x, vreg[1].y, vreg[1].z, vreg[1].w};
            float vc2[4] = {vreg[2].x, vreg[2].y, vreg[2].z, vreg[2].w};
            float vd[4] = {vreg[3].x, vreg[3].y, vreg[3].z, vreg[3].w};
            uint4 h0, h1, l0u, l1u;
            unsigned *h0p = (unsigned*)&h0, *h1p = (unsigned*)&h1;
            unsigned *l0p = (unsigned*)&l0u, *l1p = (unsigned*)&l1u;
#pragma unroll
            for (int e = 0; e < 4; ++e) {
                unsigned ph = packbf(va[e], vc2[e]);
                h0p[e] = ph;
                l0p[e] = packbf(va[e] - lo16f(ph), vc2[e] - hi16f(ph));
                unsigned ph2 = packbf(vb[e], vd[e]);
                h1p[e] = ph2;
                l1p[e] = packbf(vb[e] - lo16f(ph2), vd[e] - hi16f(ph2));
            }
            *(uint4*)&Vph[jp * WS + vc]     = h0;
            *(uint4*)&Vph[jp * WS + vc + 4] = h1;
            *(uint4*)&Vpl[jp * WS + vc]     = l0u;
            *(uint4*)&Vpl[jp * WS + vc + 4] = l1u;
        }

        __syncthreads();  // (B) converted tiles visible

        // Prefetch next tile's K/V into registers
        if (j0 + BJ < S_LEN) {
#pragma unroll
            for (int it = 0; it < 4; ++it)
                kreg[it] = *(const float4*)&Kg[qbase + (j0 + BJ + fr + it * 16) * D_DIM + fc];
            vreg[0] = *(const float4*)&Vg[qbase + (j0 + BJ + 2 * jp)     * D_DIM + vc];
            vreg[1] = *(const float4*)&Vg[qbase + (j0 + BJ + 2 * jp)     * D_DIM + vc + 4];
            vreg[2] = *(const float4*)&Vg[qbase + (j0 + BJ + 2 * jp + 1) * D_DIM + vc];
            vreg[3] = *(const float4*)&Vg[qbase + (j0 + BJ + 2 * jp + 1) * D_DIM + vc + 4];
        }

        // Bias loads (latency hidden by QK mma)
        float2 ddv0[4], ddv1[4], eev0[4], eev1[4];
        int2   mmv0[4], mmv1[4];
        {
            int rb0 = mb + (i0 + iw + g) * S_LEN + j0 + jh;
            int rb1 = rb0 + 8 * S_LEN;
#pragma unroll
            for (int nt = 0; nt < 4; ++nt) {
                int off = nt * 8 + 2 * t;
                ddv0[nt] = *(const float2*)&Dm[rb0 + off];
                ddv1[nt] = *(const float2*)&Dm[rb1 + off];
                eev0[nt] = *(const float2*)&Em[rb0 + off];
                eev1[nt] = *(const float2*)&Em[rb1 + off];
                mmv0[nt] = *(const int2*)&Mk[rb0 + off];
                mmv1[nt] = *(const int2*)&Mk[rb1 + off];
            }
        }

        // ---- QK^T: 3xTF32, operands straight from SMEM ----
        float S[4][4];
#pragma unroll
        for (int nt = 0; nt < 4; ++nt)
#pragma unroll
            for (int x = 0; x < 4; ++x) S[nt][x] = 0.f;

#pragma unroll
        for (int nt = 0; nt < 4; ++nt) {
            const unsigned* KhR = Kh + (jh + nt * 8 + g) * WS;
            const unsigned* KlR = Kl + (jh + nt * 8 + g) * WS;
#pragma unroll
            for (int kt = 0; kt < 8; ++kt) {
                unsigned kh0 = KhR[kt * 8 + t], kh1 = KhR[kt * 8 + t + 4];
                unsigned kl0 = KlR[kt * 8 + t], kl1 = KlR[kt * 8 + t + 4];
                mma_tf32(S[nt], qh[kt], kh0, kh1);
                mma_tf32(S[nt], ql[kt], kh0, kh1);
                mma_tf32(S[nt], qh[kt], kl0, kl1);
            }
        }

        // ---- bias + mask + fixed-shift softmax ----
#pragma unroll
        for (int nt = 0; nt < 4; ++nt) {
            float s0 = fmaf(S[nt][0], SCALE, lut_interp(LD, ddv0[nt].x) + lut_interp(LE, eev0[nt].x));
            float s1 = fmaf(S[nt][1], SCALE, lut_interp(LD, ddv0[nt].y) + lut_interp(LE, eev0[nt].y));
            float s2 = fmaf(S[nt][2], SCALE, lut_interp(LD, ddv1[nt].x) + lut_interp(LE, eev1[nt].x));
            float s3 = fmaf(S[nt][3], SCALE, lut_interp(LD, ddv1[nt].y) + lut_interp(LE, eev1[nt].y));
            s0 = (mmv0[nt].x == 0) ? -1e9f : s0;
            s1 = (mmv0[nt].y == 0) ? -1e9f : s1;
            s2 = (mmv1[nt].x == 0) ? -1e9f : s2;
            s3 = (mmv1[nt].y == 0) ? -1e9f : s3;
            float p0 = __expf(fminf(s0 - SOFTMAX_SHIFT, EXP_CLAMP));
            float p1 = __expf(fminf(s1 - SOFTMAX_SHIFT, EXP_CLAMP));
            float p2 = __expf(fminf(s2 - SOFTMAX_SHIFT, EXP_CLAMP));
            float p3 = __expf(fminf(s3 - SOFTMAX_SHIFT, EXP_CLAMP));
            l0 += p0 + p1; l1 += p2 + p3;
            S[nt][0] = p0; S[nt][1] = p1; S[nt][2] = p2; S[nt][3] = p3;
        }

        // ---- PV: 3xBF16, V operands straight from SMEM ----
#pragma unroll
        for (int ktj = 0; ktj < 2; ++ktj) {
            const float* Sa = S[2 * ktj];
            const float* Sb = S[2 * ktj + 1];
            unsigned pah[4], pal[4];
            pah[0] = packbf(Sa[0], Sa[1]); pal[0] = packbf(Sa[0] - lo16f(pah[0]), Sa[1] - hi16f(pah[0]));
            pah[1] = packbf(Sa[2], Sa[3]); pal[1] = packbf(Sa[2] - lo16f(pah[1]), Sa[3] - hi16f(pah[1]));
            pah[2] = packbf(Sb[0], Sb[1]); pal[2] = packbf(Sb[0] - lo16f(pah[2]), Sb[1] - hi16f(pah[2]));
            pah[3] = packbf(Sb[2], Sb[3]); pal[3] = packbf(Sb[2] - lo16f(pah[3]), Sb[3] - hi16f(pah[3]));

            int jpb = jh / 2 + ktj * 8;   // j-pair base for this k16 chunk
            const unsigned* Vh0 = Vph + (jpb + t)     * WS + g;
            const unsigned* Vh1 = Vph + (jpb + t + 4) * WS + g;
            const unsigned* Vl0 = Vpl + (jpb + t)     * WS + g;
            const unsigned* Vl1 = Vpl + (jpb + t + 4) * WS + g;
#pragma unroll
            for (int nt = 0; nt < 8; ++nt) {
                unsigned vh0 = Vh0[nt * 8], vh1 = Vh1[nt * 8];
                unsigned vl0 = Vl0[nt * 8], vl1 = Vl1[nt * 8];
                mma_bf16(O[nt], pah, vh0, vh1);
                mma_bf16(O[nt], pal, vh0, vh1);
                mma_bf16(O[nt], pah, vl0, vl1);
            }
        }
    }

    // ---- Epilogue: merge j-halves, reduce l, normalize, write ----
    __syncthreads();                  // all mma reads of Kh done before scratch reuse
    float* scratch = sm;              // reuse Kh region: 34 x 128 f32 = 17408B
    int slot = (wid & 3) * 32 + lane;
    if (wid >= 4) {
#pragma unroll
        for (int nt = 0; nt < 8; ++nt)
#pragma unroll
            for (int x = 0; x < 4; ++x)
                scratch[(nt * 4 + x) * 128 + slot] = O[nt][x];
        scratch[32 * 128 + slot] = l0;
        scratch[33 * 128 + slot] = l1;
    }
    __syncthreads();
    if (wid < 4) {
#pragma unroll
        for (int nt = 0; nt < 8; ++nt)
#pragma unroll
            for (int x = 0; x < 4; ++x)
                O[nt][x] += scratch[(nt * 4 + x) * 128 + slot];
        l0 += scratch[32 * 128 + slot];
        l1 += scratch[33 * 128 + slot];
        l0 += __shfl_xor_sync(0xffffffffu, l0, 1);
        l0 += __shfl_xor_sync(0xffffffffu, l0, 2);
        l1 += __shfl_xor_sync(0xffffffffu, l1, 1);
        l1 += __shfl_xor_sync(0xffffffffu, l1, 2);
        float inv0 = 1.0f / l0, inv1 = 1.0f / l1;
        int r0 = qbase + (i0 + iw + g) * D_DIM;
        int r1 = qbase + (i0 + iw + g + 8) * D_DIM;
#pragma unroll
        for (int nt = 0; nt < 8; ++nt) {
            int c = nt * 8 + 2 * t;
            *(float2*)&Out[r0 + c] = make_float2(O[nt][0] * inv0, O[nt][1] * inv0);
            *(float2*)&Out[r1 + c] = make_float2(O[nt][2] * inv1, O[nt][3] * inv1);
        }
    }
}

// SMEM: (64*WS)*2 u32 (Kh,Kl) + (32*WS)*2 u32 (Vph,Vpl) + 2 LUTs of 2048 float2
#define SMEM_BYTES ((64 * WS * 2 + 32 * WS * 2) * 4 + 2 * NLUT * 8)

extern "C" void kernel_launch(void* const* d_in, const int* in_sizes, int n_in,
                              void* d_out, int out_size)
{
    const float* Q   = (const float*)d_in[0];
    const float* K   = (const float*)d_in[1];
    const float* V   = (const float*)d_in[2];
    const float* Dm  = (const float*)d_in[3];
    const float* Em  = (const float*)d_in[4];
    const int*   Mk  = (const int*)  d_in[5];
    const float* muD = (const float*)d_in[6];
    const float* sgD = (const float*)d_in[7];
    const float* bD  = (const float*)d_in[8];
    const float* muE = (const float*)d_in[9];
    const float* sgE = (const float*)d_in[10];
    const float* bE  = (const float*)d_in[11];
    const float* W1  = (const float*)d_in[12];
    const float* b1  = (const float*)d_in[13];
    const float* W2  = (const float*)d_in[14];
    const float* b2  = (const float*)d_in[15];
    float* Out = (float*)d_out;

    cudaFuncSetAttribute(attn_kernel, cudaFuncAttributeMaxDynamicSharedMemorySize, SMEM_BYTES);

    build_lut_kernel<<<(2 * NLUT + 255) / 256, 256>>>(muD, sgD, bD, muE, sgE, bE, W1, b1, W2, b2);

    dim3 grid(S_LEN / BI, H_NUM);   // 16 x 8 = 128 CTAs
    attn_kernel<<<grid, 256, SMEM_BYTES>>>(Q, K, V, Dm, Em, Mk, Out);
}